// round 1
// baseline (speedup 1.0000x reference)
#include <cuda_runtime.h>

// Problem constants (fixed by the reference)
#define BB 4
#define CC 128
#define DD 32
#define SS 4096   // H*W
#define NN 128    // B*D

// Shared memory layout (floats):
//  R1 = sm[0      .. 16384)  : phase1 Vk tile (first 4096) -> then At[m][c] (128x128)
//  R2 = sm[16384  .. 32768)  : phase1 energy E[c][m]      -> then Vt[m][64] tile (8192)
//  invs = sm[32768 .. 32896) : per-row 1/sum for softmax normalization
#define SMEM_FLOATS (32768 + 128)
#define SMEM_BYTES  (SMEM_FLOATS * 4)

__global__ __launch_bounds__(256, 1)
void cam_fused_kernel(const float* __restrict__ x,
                      const float* __restrict__ gamma,
                      float* __restrict__ out)
{
    extern __shared__ float sm[];
    float* R1   = sm;
    float* R2   = sm + 16384;
    float* invs = sm + 32768;

    const int n  = blockIdx.x;          // n = b*D + d
    const int b  = n / DD;
    const int d  = n % DD;
    const int tid = threadIdx.x;
    const int tx = tid & 15;
    const int ty = tid >> 4;

    // channel-row base: x[((b*C + c)*D + d)*S + s]; row (c) is contiguous in s
    const float*  xbase   = x + ((size_t)(b * CC) * DD + d) * SS;
    const size_t  cstride = (size_t)DD * SS;   // stride between channel rows

    // ---------------- Phase 1: E = V * V^T  (128x128, K=4096) ----------------
    float acc[8][8];
#pragma unroll
    for (int u = 0; u < 8; u++)
#pragma unroll
        for (int v = 0; v < 8; v++) acc[u][v] = 0.f;

    float* Vk = R1;                     // [32][128], k-major
    const int   lrow  = tid >> 1;       // 0..127  (channel)
    const int   lkoff = (tid & 1) * 16; // which half of the 32-wide k chunk
    const float* lptr = xbase + (size_t)lrow * cstride;

    for (int kc = 0; kc < SS; kc += 32) {
        // load 128x32 chunk, transposed into Vk[k][c]
#pragma unroll
        for (int p = 0; p < 4; p++) {
            const int kk = lkoff + p * 4;
            float4 vv = *reinterpret_cast<const float4*>(lptr + kc + kk);
            Vk[(kk + 0) * 128 + lrow] = vv.x;
            Vk[(kk + 1) * 128 + lrow] = vv.y;
            Vk[(kk + 2) * 128 + lrow] = vv.z;
            Vk[(kk + 3) * 128 + lrow] = vv.w;
        }
        __syncthreads();

#pragma unroll
        for (int kk = 0; kk < 32; kk++) {
            const float* row = &Vk[kk * 128];
            float4 a0 = *reinterpret_cast<const float4*>(row + ty * 8);
            float4 a1 = *reinterpret_cast<const float4*>(row + ty * 8 + 4);
            float4 b0 = *reinterpret_cast<const float4*>(row + tx * 8);
            float4 b1 = *reinterpret_cast<const float4*>(row + tx * 8 + 4);
            float av[8] = {a0.x, a0.y, a0.z, a0.w, a1.x, a1.y, a1.z, a1.w};
            float bv[8] = {b0.x, b0.y, b0.z, b0.w, b1.x, b1.y, b1.z, b1.w};
#pragma unroll
            for (int u = 0; u < 8; u++)
#pragma unroll
                for (int v = 0; v < 8; v++)
                    acc[u][v] += av[u] * bv[v];
        }
        __syncthreads();
    }

    // stash energy into R2: E[i][j]
#pragma unroll
    for (int u = 0; u < 8; u++) {
        const int i = ty * 8 + u;
#pragma unroll
        for (int v = 0; v < 8; v++)
            R2[i * 128 + tx * 8 + v] = acc[u][v];
    }
    __syncthreads();

    // ---------------- Softmax:  A = softmax(rowmax - E) = softmin(E) ----------------
    // attention[c][m] = exp(rowmin_c - E[c][m]) / sum_m exp(rowmin_c - E[c][m])
    // Store UNNORMALIZED, TRANSPOSED At[m][c] in R1; fold 1/sum into epilogue.
    if (tid < 128) {
        const float* Er = R2 + tid * 128;
        float mn = Er[0];
#pragma unroll 4
        for (int m = 1; m < 128; m++) mn = fminf(mn, Er[m]);
        float sum = 0.f;
#pragma unroll 4
        for (int m = 0; m < 128; m++) {
            float p = __expf(mn - Er[m]);
            sum += p;
            R1[m * 128 + tid] = p;      // At[m][r], conflict-free column write
        }
        invs[tid] = 1.0f / sum;
    }
    __syncthreads();

    // ---------------- Phase 2: out = A * V, epilogue gamma*out + V ----------------
    const float g = gamma[0];
    float* At = R1;            // [128][128]  (At[m][c] = unnormalized A[c][m])
    float* Vt = R2;            // [128][64]
    float* outbase = out + (size_t)n * CC * SS;

    const int  vrow = tid >> 1;
    const int  voff = (tid & 1) * 32;
    const float* vptr = xbase + (size_t)vrow * cstride;

    for (int sc = 0; sc < SS; sc += 64) {
        // stream V tile [128 m][64 s]
#pragma unroll
        for (int p = 0; p < 8; p++) {
            const int ssoff = voff + p * 4;
            float4 vv = *reinterpret_cast<const float4*>(vptr + sc + ssoff);
            *reinterpret_cast<float4*>(&Vt[vrow * 64 + ssoff]) = vv;
        }
        __syncthreads();

        float acc2[8][4];
#pragma unroll
        for (int u = 0; u < 8; u++)
#pragma unroll
            for (int v = 0; v < 4; v++) acc2[u][v] = 0.f;

#pragma unroll 8
        for (int m = 0; m < 128; m++) {
            float4 a0 = *reinterpret_cast<const float4*>(&At[m * 128 + ty * 8]);
            float4 a1 = *reinterpret_cast<const float4*>(&At[m * 128 + ty * 8 + 4]);
            float4 bb = *reinterpret_cast<const float4*>(&Vt[m * 64 + tx * 4]);
            float av[8] = {a0.x, a0.y, a0.z, a0.w, a1.x, a1.y, a1.z, a1.w};
            float bv[4] = {bb.x, bb.y, bb.z, bb.w};
#pragma unroll
            for (int u = 0; u < 8; u++)
#pragma unroll
                for (int v = 0; v < 4; v++)
                    acc2[u][v] += av[u] * bv[v];
        }

        // epilogue: out[c][s] = g * (acc2 * inv[c]) + V[c][s]
#pragma unroll
        for (int u = 0; u < 8; u++) {
            const int c = ty * 8 + u;
            const float iv = invs[c] * g;
            float4 vv = *reinterpret_cast<const float4*>(
                xbase + (size_t)c * cstride + sc + tx * 4);
            float4 o;
            o.x = acc2[u][0] * iv + vv.x;
            o.y = acc2[u][1] * iv + vv.y;
            o.z = acc2[u][2] * iv + vv.z;
            o.w = acc2[u][3] * iv + vv.w;
            *reinterpret_cast<float4*>(outbase + (size_t)c * SS + sc + tx * 4) = o;
        }
        __syncthreads();
    }
}

extern "C" void kernel_launch(void* const* d_in, const int* in_sizes, int n_in,
                              void* d_out, int out_size)
{
    const float* x     = (const float*)d_in[0];
    const float* gamma = (const float*)d_in[1];
    float* out = (float*)d_out;

    cudaFuncSetAttribute(cam_fused_kernel,
                         cudaFuncAttributeMaxDynamicSharedMemorySize, SMEM_BYTES);
    cam_fused_kernel<<<NN, 256, SMEM_BYTES>>>(x, gamma, out);
}

// round 3
// speedup vs baseline: 1.2234x; 1.2234x over previous
#include <cuda_runtime.h>

// Problem constants (fixed by the reference)
#define BB 4
#define CC 128
#define DD 32
#define SS 4096   // H*W
#define NN 128    // B*D

// Shared memory layout (floats):
//  R1 = sm[0      .. 16384) : phase1 Vk double buffer (2x4096) -> later At[m][c] (128x128)
//  R2 = sm[16384 .. 32768)  : phase1 energy E[c][m] -> later Vt double buffer (2x8192)
//  invs = sm[32768 .. 32896): per-row gamma/sum for softmax normalization
#define SMEM_FLOATS (32768 + 128)
#define SMEM_BYTES  (SMEM_FLOATS * 4)

typedef unsigned long long u64;

__device__ __forceinline__ u64 pack2(float lo, float hi) {
    u64 r;
    asm("mov.b64 %0, {%1, %2};" : "=l"(r) : "f"(lo), "f"(hi));
    return r;
}
__device__ __forceinline__ u64 dup2(float v) { return pack2(v, v); }
__device__ __forceinline__ void fma2(u64& d, u64 a, u64 b) {
    asm("fma.rn.f32x2 %0, %1, %2, %3;" : "=l"(d) : "l"(a), "l"(b), "l"(d));
}
__device__ __forceinline__ void unpack2(u64 v, float& lo, float& hi) {
    asm("mov.b64 {%0, %1}, %2;" : "=f"(lo), "=f"(hi) : "l"(v));
}

__global__ __launch_bounds__(256, 1)
void cam_fused_kernel(const float* __restrict__ x,
                      const float* __restrict__ gamma,
                      float* __restrict__ out)
{
    extern __shared__ float sm[];
    float* R1   = sm;           // 16384 floats
    float* R2   = sm + 16384;   // 16384 floats
    float* invs = sm + 32768;   // 128 floats

    const int n   = blockIdx.x;       // n = b*D + d
    const int b   = n / DD;
    const int d   = n % DD;
    const int tid = threadIdx.x;
    const int tx  = tid & 15;
    const int ty  = tid >> 4;

    // channel-row base: x[((b*C + c)*D + d)*S + s]; row (c) is contiguous in s
    const float* xbase   = x + ((size_t)(b * CC) * DD + d) * SS;
    const size_t cstride = (size_t)DD * SS;

    // ---------------- Phase 1: E = V * V^T  (128x128, K=4096) ----------------
    // acc pairs along the v (tx) dimension: acc[u][vp] holds (v=2vp, v=2vp+1)
    u64 acc[8][4];
#pragma unroll
    for (int u = 0; u < 8; u++)
#pragma unroll
        for (int vp = 0; vp < 4; vp++) acc[u][vp] = 0ull;

    const int    lrow  = tid >> 1;        // 0..127 (channel)
    const int    lkoff = (tid & 1) * 16;  // half of the 32-wide k chunk
    const float* lptr  = xbase + (size_t)lrow * cstride;

    // prefetch chunk 0
    float4 pf[4];
#pragma unroll
    for (int p = 0; p < 4; p++)
        pf[p] = *reinterpret_cast<const float4*>(lptr + lkoff + p * 4);

    int buf = 0;
    for (int kc = 0; kc < SS; kc += 32) {
        float* Vkb = R1 + (buf ? 4096 : 0);   // [32][128] k-major
        // store prefetched chunk (transposed)
#pragma unroll
        for (int p = 0; p < 4; p++) {
            const int kk = lkoff + p * 4;
            Vkb[(kk + 0) * 128 + lrow] = pf[p].x;
            Vkb[(kk + 1) * 128 + lrow] = pf[p].y;
            Vkb[(kk + 2) * 128 + lrow] = pf[p].z;
            Vkb[(kk + 3) * 128 + lrow] = pf[p].w;
        }
        // prefetch next chunk (latency hidden behind compute)
        if (kc + 32 < SS) {
#pragma unroll
            for (int p = 0; p < 4; p++)
                pf[p] = *reinterpret_cast<const float4*>(lptr + kc + 32 + lkoff + p * 4);
        }
        __syncthreads();

#pragma unroll
        for (int kk = 0; kk < 32; kk++) {
            const float* row = &Vkb[kk * 128];
            float4 a0 = *reinterpret_cast<const float4*>(row + ty * 8);
            float4 a1 = *reinterpret_cast<const float4*>(row + ty * 8 + 4);
            float4 b0 = *reinterpret_cast<const float4*>(row + tx * 8);
            float4 b1 = *reinterpret_cast<const float4*>(row + tx * 8 + 4);
            u64 bb[4];
            bb[0] = pack2(b0.x, b0.y);
            bb[1] = pack2(b0.z, b0.w);
            bb[2] = pack2(b1.x, b1.y);
            bb[3] = pack2(b1.z, b1.w);
            u64 aa[8];
            aa[0] = dup2(a0.x); aa[1] = dup2(a0.y);
            aa[2] = dup2(a0.z); aa[3] = dup2(a0.w);
            aa[4] = dup2(a1.x); aa[5] = dup2(a1.y);
            aa[6] = dup2(a1.z); aa[7] = dup2(a1.w);
#pragma unroll
            for (int u = 0; u < 8; u++)
#pragma unroll
                for (int vp = 0; vp < 4; vp++)
                    fma2(acc[u][vp], aa[u], bb[vp]);
        }
        buf ^= 1;
        // no trailing sync needed: next store targets the other buffer
    }

    // stash energy into R2: E[i][j] (paired stores, 8-byte aligned)
#pragma unroll
    for (int u = 0; u < 8; u++) {
        const int i = ty * 8 + u;
#pragma unroll
        for (int vp = 0; vp < 4; vp++)
            *reinterpret_cast<u64*>(&R2[i * 128 + tx * 8 + vp * 2]) = acc[u][vp];
    }
    __syncthreads();

    // ---------------- Softmax: A = softmax(rowmax - E) = softmin(E) ----------------
    // Store UNNORMALIZED, TRANSPOSED At[m][c] in R1; fold gamma/sum into epilogue.
    const float g = gamma[0];
    if (tid < 128) {
        const float* Er = R2 + tid * 128;
        float mn = Er[0];
#pragma unroll 4
        for (int m = 1; m < 128; m++) mn = fminf(mn, Er[m]);
        float sum = 0.f;
#pragma unroll 4
        for (int m = 0; m < 128; m++) {
            float p = __expf(mn - Er[m]);
            sum += p;
            R1[m * 128 + tid] = p;      // At[m][r], conflict-free column write
        }
        invs[tid] = g / sum;
    }
    __syncthreads();

    // ---------------- Phase 2: out = A * V, epilogue gamma*out + V ----------------
    float* At = R1;                 // [128][128]  At[m][c] = unnormalized A[c][m]
    float* outbase = out + (size_t)n * CC * SS;

    const int    vrow = tid >> 1;
    const int    voff = (tid & 1) * 32;
    const float* vptr = xbase + (size_t)vrow * cstride;

    // prefetch V chunk 0
    float4 pf2[8];
#pragma unroll
    for (int p = 0; p < 8; p++)
        pf2[p] = *reinterpret_cast<const float4*>(vptr + voff + p * 4);

    int buf2 = 0;
    for (int sc = 0; sc < SS; sc += 64) {
        float* Vtb = R2 + (buf2 ? 8192 : 0);  // [128][64]
        // store prefetched tile
#pragma unroll
        for (int p = 0; p < 8; p++)
            *reinterpret_cast<float4*>(&Vtb[vrow * 64 + voff + p * 4]) = pf2[p];
        // prefetch next tile
        if (sc + 64 < SS) {
#pragma unroll
            for (int p = 0; p < 8; p++)
                pf2[p] = *reinterpret_cast<const float4*>(vptr + sc + 64 + voff + p * 4);
        }
        __syncthreads();

        u64 acc2[8][2];
#pragma unroll
        for (int u = 0; u < 8; u++) {
            acc2[u][0] = 0ull;
            acc2[u][1] = 0ull;
        }

#pragma unroll 8
        for (int m = 0; m < 128; m++) {
            float4 a0 = *reinterpret_cast<const float4*>(&At[m * 128 + ty * 8]);
            float4 a1 = *reinterpret_cast<const float4*>(&At[m * 128 + ty * 8 + 4]);
            float4 bv = *reinterpret_cast<const float4*>(&Vtb[m * 64 + tx * 4]);
            u64 bb0 = pack2(bv.x, bv.y);
            u64 bb1 = pack2(bv.z, bv.w);
            u64 aa[8];
            aa[0] = dup2(a0.x); aa[1] = dup2(a0.y);
            aa[2] = dup2(a0.z); aa[3] = dup2(a0.w);
            aa[4] = dup2(a1.x); aa[5] = dup2(a1.y);
            aa[6] = dup2(a1.z); aa[7] = dup2(a1.w);
#pragma unroll
            for (int u = 0; u < 8; u++) {
                fma2(acc2[u][0], aa[u], bb0);
                fma2(acc2[u][1], aa[u], bb1);
            }
        }

        // epilogue: out[c][s] = (gamma/sum_c) * acc2 + V[c][s]  (V from smem tile)
#pragma unroll
        for (int u = 0; u < 8; u++) {
            const int c  = ty * 8 + u;
            const float iv = invs[c];
            float o0, o1, o2, o3;
            unpack2(acc2[u][0], o0, o1);
            unpack2(acc2[u][1], o2, o3);
            float4 vv = *reinterpret_cast<const float4*>(&Vtb[c * 64 + tx * 4]);
            float4 o;
            o.x = fmaf(o0, iv, vv.x);
            o.y = fmaf(o1, iv, vv.y);
            o.z = fmaf(o2, iv, vv.z);
            o.w = fmaf(o3, iv, vv.w);
            *reinterpret_cast<float4*>(outbase + (size_t)c * SS + sc + tx * 4) = o;
        }
        buf2 ^= 1;
        // next store targets the other buffer; no trailing sync needed
    }
}

extern "C" void kernel_launch(void* const* d_in, const int* in_sizes, int n_in,
                              void* d_out, int out_size)
{
    const float* x     = (const float*)d_in[0];
    const float* gamma = (const float*)d_in[1];
    float* out = (float*)d_out;

    cudaFuncSetAttribute(cam_fused_kernel,
                         cudaFuncAttributeMaxDynamicSharedMemorySize, SMEM_BYTES);
    cam_fused_kernel<<<NN, 256, SMEM_BYTES>>>(x, gamma, out);
}

// round 5
// speedup vs baseline: 2.8581x; 2.3362x over previous
#include <cuda_runtime.h>
#include <cstdint>

// Problem constants
#define CCk 128
#define DDk 32
#define SSk 4096

// ---------------- smem byte layout ----------------
// Phase1 V stages: stage s at s*32KB: hi tile [128r][64k] bf16 (16KB) + lo at +16KB.
// A (after softmin) reuses [0,64KB): hi blk(k>>6) at blk*16KB; lo at +32KB.
// E: f32 [128][132] at 64KB (67584 B) — overlaps B stages (sequential use).
// Phase2 B stages: stage s at 64KB + s*32KB: hi [128 m'][64 s] + lo at +16KB.
// inv: 128 f32 at 133120.
#define P1STAGE(s)  ((uint32_t)(s) * 32768u)
#define BSTAGE(s)   (65536u + (uint32_t)(s) * 32768u)
#define EOFF        65536u
#define ESTRIDE     132
#define IVOFF       133120u
#define SMEMSZ      (133120u + 512u)

#define SWZ(o) ((o) ^ (((o) >> 3) & 0x70u))

static __device__ __forceinline__ uint32_t s2u(const void* p) {
    uint32_t a;
    asm("{ .reg .u64 t; cvta.to.shared.u64 t, %1; cvt.u32.u64 %0, t; }"
        : "=r"(a) : "l"(p));
    return a;
}

static __device__ __forceinline__ void ldsm4(uint32_t* r, uint32_t addr) {
    asm volatile("ldmatrix.sync.aligned.m8n8.x4.shared.b16 {%0,%1,%2,%3}, [%4];"
        : "=r"(r[0]), "=r"(r[1]), "=r"(r[2]), "=r"(r[3]) : "r"(addr));
}
static __device__ __forceinline__ void ldsm4t(uint32_t* r, uint32_t addr) {
    asm volatile("ldmatrix.sync.aligned.m8n8.x4.trans.shared.b16 {%0,%1,%2,%3}, [%4];"
        : "=r"(r[0]), "=r"(r[1]), "=r"(r[2]), "=r"(r[3]) : "r"(addr));
}
static __device__ __forceinline__ void mma16816(float* c, const uint32_t* a,
                                                uint32_t b0, uint32_t b1) {
    asm volatile(
        "mma.sync.aligned.m16n8k16.row.col.f32.bf16.bf16.f32 "
        "{%0,%1,%2,%3}, {%4,%5,%6,%7}, {%8,%9}, {%0,%1,%2,%3};"
        : "+f"(c[0]), "+f"(c[1]), "+f"(c[2]), "+f"(c[3])
        : "r"(a[0]), "r"(a[1]), "r"(a[2]), "r"(a[3]), "r"(b0), "r"(b1));
}

// split 2 fp32 -> packed bf16x2 hi (elem order: f0 low half) + lo (residual)
static __device__ __forceinline__ void split2(float f0, float f1, uint32_t& hp, uint32_t& lp) {
    asm("cvt.rn.bf16x2.f32 %0, %1, %2;" : "=r"(hp) : "f"(f1), "f"(f0));
    float h0 = __uint_as_float(hp << 16);
    float h1 = __uint_as_float(hp & 0xffff0000u);
    asm("cvt.rn.bf16x2.f32 %0, %1, %2;" : "=r"(lp) : "f"(f1 - h1), "f"(f0 - h0));
}
static __device__ __forceinline__ void split8(float4 a, float4 b, uint4& hi, uint4& lo) {
    split2(a.x, a.y, hi.x, lo.x);
    split2(a.z, a.w, hi.y, lo.y);
    split2(b.x, b.y, hi.z, lo.z);
    split2(b.z, b.w, hi.w, lo.w);
}
static __device__ __forceinline__ float2 bfpair(uint32_t w) {
    float2 r;
    r.x = __uint_as_float(w << 16);
    r.y = __uint_as_float(w & 0xffff0000u);
    return r;
}

__global__ __launch_bounds__(256, 1)
void cam_mma_kernel(const float* __restrict__ x,
                    const float* __restrict__ gamma,
                    float* __restrict__ out)
{
    extern __shared__ __align__(1024) uint8_t sm[];
    const uint32_t smb = s2u(sm);

    const int tid  = threadIdx.x;
    const int lane = tid & 31;
    const int wid  = tid >> 5;
    const int wm   = wid & 3;      // m block: rows 32*wm
    const int wn   = wid >> 2;     // n block
    const int m0   = wm * 32;

    const int n = blockIdx.x;
    const int b = n / DDk, d = n % DDk;
    const float* xbase = x + ((size_t)(b * CCk) * DDk + d) * (size_t)SSk;
    const size_t cstride = (size_t)DDk * SSk;
    float* outbase = out + (size_t)n * CCk * SSk;

    const int r = tid >> 1, h = tid & 1;       // conversion mapping: row r, k/s half h
    const float* rowp = xbase + (size_t)r * cstride;

    // =============== Phase 1: E = V * V^T (K = 4096, chunks of 64) ===============
    float acc[2][8][4];
#pragma unroll
    for (int mt = 0; mt < 2; mt++)
#pragma unroll
        for (int nt = 0; nt < 8; nt++)
#pragma unroll
            for (int q = 0; q < 4; q++) acc[mt][nt][q] = 0.f;

    const int n0 = wn * 64;

    float4 pf[8];
#pragma unroll
    for (int p = 0; p < 8; p++)
        pf[p] = *reinterpret_cast<const float4*>(rowp + h * 32 + p * 4);

    for (int kc = 0; kc < 64; kc++) {
        uint8_t* hb = sm + P1STAGE(kc & 1);
        uint8_t* lb = hb + 16384;
#pragma unroll
        for (int g = 0; g < 4; g++) {
            uint4 hi4, lo4;
            split8(pf[2 * g], pf[2 * g + 1], hi4, lo4);
            uint32_t off = SWZ((uint32_t)(r * 128 + h * 64 + g * 16));
            *reinterpret_cast<uint4*>(hb + off) = hi4;
            *reinterpret_cast<uint4*>(lb + off) = lo4;
        }
        __syncthreads();
        if (kc + 1 < 64) {
#pragma unroll
            for (int p = 0; p < 8; p++)
                pf[p] = *reinterpret_cast<const float4*>(rowp + (kc + 1) * 64 + h * 32 + p * 4);
        }
        const uint32_t hbu = smb + P1STAGE(kc & 1);
        const uint32_t lbu = hbu + 16384u;
#pragma unroll
        for (int kk = 0; kk < 4; kk++) {
            uint32_t ah[2][4], al[2][4], bh[4][4], bl[4][4];
#pragma unroll
            for (int mt = 0; mt < 2; mt++) {
                int rowA = m0 + mt * 16 + (lane & 15);
                int ch = kk * 2 + (lane >> 4);
                uint32_t off = SWZ((uint32_t)(rowA * 128 + ch * 16));
                ldsm4(ah[mt], hbu + off);
                ldsm4(al[mt], lbu + off);
            }
#pragma unroll
            for (int bt = 0; bt < 4; bt++) {
                int rowB = n0 + bt * 16 + ((lane >> 4) & 1) * 8 + (lane & 7);
                int ch = kk * 2 + ((lane >> 3) & 1);
                uint32_t off = SWZ((uint32_t)(rowB * 128 + ch * 16));
                ldsm4(bh[bt], hbu + off);
                ldsm4(bl[bt], lbu + off);
            }
#pragma unroll
            for (int mt = 0; mt < 2; mt++)
#pragma unroll
                for (int nt = 0; nt < 8; nt++) {
                    uint32_t b0h = bh[nt >> 1][(nt & 1) * 2];
                    uint32_t b1h = bh[nt >> 1][(nt & 1) * 2 + 1];
                    uint32_t b0l = bl[nt >> 1][(nt & 1) * 2];
                    uint32_t b1l = bl[nt >> 1][(nt & 1) * 2 + 1];
                    mma16816(acc[mt][nt], ah[mt], b0h, b1h);
                    mma16816(acc[mt][nt], ah[mt], b0l, b1l);
                    mma16816(acc[mt][nt], al[mt], b0h, b1h);
                }
        }
    }

    // spill E to smem (c-frag mapping: row = base + lane/4 (+8), col = base + 2*(lane%4))
    {
        float* E = reinterpret_cast<float*>(sm + EOFF);
#pragma unroll
        for (int mt = 0; mt < 2; mt++)
#pragma unroll
            for (int nt = 0; nt < 8; nt++) {
                int row = m0 + mt * 16 + (lane >> 2);
                int col = n0 + nt * 8 + (lane & 3) * 2;
                float2 v01 = make_float2(acc[mt][nt][0], acc[mt][nt][1]);
                float2 v23 = make_float2(acc[mt][nt][2], acc[mt][nt][3]);
                *reinterpret_cast<float2*>(&E[row * ESTRIDE + col]) = v01;
                *reinterpret_cast<float2*>(&E[(row + 8) * ESTRIDE + col]) = v23;
            }
    }
    __syncthreads();

    // prefetch phase2 chunk 0 while softmin runs
    float4 pf2[8];
#pragma unroll
    for (int p = 0; p < 8; p++)
        pf2[p] = *reinterpret_cast<const float4*>(rowp + h * 32 + p * 4);

    // =============== Softmin: A[c][m] = exp(min_c - E[c][m]); write A hi/lo ===============
    if (tid < 128) {
        const int c = tid;
        const float* Er = reinterpret_cast<const float*>(sm + EOFF) + c * ESTRIDE;
        float mn = Er[0];
#pragma unroll 4
        for (int m = 1; m < 128; m++) mn = fminf(mn, Er[m]);
        float sum = 0.f;
#pragma unroll
        for (int mg = 0; mg < 16; mg++) {
            float p[8];
#pragma unroll
            for (int q = 0; q < 8; q++) {
                p[q] = __expf(mn - Er[mg * 8 + q]);
                sum += p[q];
            }
            uint4 hi4, lo4;
            split2(p[0], p[1], hi4.x, lo4.x);
            split2(p[2], p[3], hi4.y, lo4.y);
            split2(p[4], p[5], hi4.z, lo4.z);
            split2(p[6], p[7], hi4.w, lo4.w);
            const int m = mg * 8;
            uint32_t off = (uint32_t)(m >> 6) * 16384u
                         + SWZ((uint32_t)(c * 128 + (m & 63) * 2));
            *reinterpret_cast<uint4*>(sm + off) = hi4;            // A hi
            *reinterpret_cast<uint4*>(sm + 32768u + off) = lo4;   // A lo
        }
        reinterpret_cast<float*>(sm + IVOFF)[c] = gamma[0] / sum;
    }
    __syncthreads();

    // =============== Phase 2: out = A * V (s chunks of 64, k = 128) ===============
    const uint32_t Ah = smb;
    const uint32_t Al = smb + 32768u;
    const int sn0 = wn * 32;   // warp's s offset within the 64-wide chunk

    for (int sc = 0; sc < 64; sc++) {
        uint8_t* hb = sm + BSTAGE(sc & 1);
        uint8_t* lb = hb + 16384;
#pragma unroll
        for (int g = 0; g < 4; g++) {
            uint4 hi4, lo4;
            split8(pf2[2 * g], pf2[2 * g + 1], hi4, lo4);
            uint32_t off = SWZ((uint32_t)(r * 128 + h * 64 + g * 16));
            *reinterpret_cast<uint4*>(hb + off) = hi4;
            *reinterpret_cast<uint4*>(lb + off) = lo4;
        }
        __syncthreads();
        if (sc + 1 < 64) {
#pragma unroll
            for (int p = 0; p < 8; p++)
                pf2[p] = *reinterpret_cast<const float4*>(rowp + (sc + 1) * 64 + h * 32 + p * 4);
        }

        float c2[2][4][4];
#pragma unroll
        for (int mt = 0; mt < 2; mt++)
#pragma unroll
            for (int nt = 0; nt < 4; nt++)
#pragma unroll
                for (int q = 0; q < 4; q++) c2[mt][nt][q] = 0.f;

        const uint32_t Bh = smb + BSTAGE(sc & 1);
        const uint32_t Bl = Bh + 16384u;
#pragma unroll
        for (int kk = 0; kk < 8; kk++) {
            uint32_t ah[2][4], al[2][4], bh[2][4], bl[2][4];
#pragma unroll
            for (int mt = 0; mt < 2; mt++) {
                int rowA = m0 + mt * 16 + (lane & 15);
                int ch = (kk & 3) * 2 + (lane >> 4);
                uint32_t off = (uint32_t)(kk >> 2) * 16384u
                             + SWZ((uint32_t)(rowA * 128 + ch * 16));
                ldsm4(ah[mt], Ah + off);
                ldsm4(al[mt], Al + off);
            }
#pragma unroll
            for (int bt = 0; bt < 2; bt++) {
                int rowB = kk * 16 + (lane & 15);      // m' rows
                int sch = wn * 4 + bt * 2 + (lane >> 4);
                uint32_t off = SWZ((uint32_t)(rowB * 128 + sch * 16));
                ldsm4t(bh[bt], Bh + off);
                ldsm4t(bl[bt], Bl + off);
            }
#pragma unroll
            for (int mt = 0; mt < 2; mt++)
#pragma unroll
                for (int nt = 0; nt < 4; nt++) {
                    uint32_t b0h = bh[nt >> 1][(nt & 1) * 2];
                    uint32_t b1h = bh[nt >> 1][(nt & 1) * 2 + 1];
                    uint32_t b0l = bl[nt >> 1][(nt & 1) * 2];
                    uint32_t b1l = bl[nt >> 1][(nt & 1) * 2 + 1];
                    mma16816(c2[mt][nt], ah[mt], b0h, b1h);
                    mma16816(c2[mt][nt], ah[mt], b0l, b1l);
                    mma16816(c2[mt][nt], al[mt], b0h, b1h);
                }
        }

        // epilogue: out[c][s] = inv[c]*acc + V[c][s] (V reconstructed from hi+lo tile)
        const float* ivp = reinterpret_cast<const float*>(sm + IVOFF);
#pragma unroll
        for (int mt = 0; mt < 2; mt++)
#pragma unroll
            for (int nt = 0; nt < 4; nt++) {
                int row = m0 + mt * 16 + (lane >> 2);
                int scol = sn0 + nt * 8 + (lane & 3) * 2;
#pragma unroll
                for (int half = 0; half < 2; half++) {
                    int c = row + half * 8;
                    float iv = ivp[c];
                    uint32_t offv = SWZ((uint32_t)(c * 128 + scol * 2));
                    float2 vh = bfpair(*reinterpret_cast<const uint32_t*>(hb + offv));
                    float2 vl = bfpair(*reinterpret_cast<const uint32_t*>(lb + offv));
                    float2 o;
                    o.x = fmaf(c2[mt][nt][half * 2 + 0], iv, vh.x + vl.x);
                    o.y = fmaf(c2[mt][nt][half * 2 + 1], iv, vh.y + vl.y);
                    *reinterpret_cast<float2*>(outbase + (size_t)c * SSk + sc * 64 + scol) = o;
                }
            }
    }
}

extern "C" void kernel_launch(void* const* d_in, const int* in_sizes, int n_in,
                              void* d_out, int out_size)
{
    const float* x     = (const float*)d_in[0];
    const float* gamma = (const float*)d_in[1];
    float* out = (float*)d_out;

    cudaFuncSetAttribute(cam_mma_kernel,
                         cudaFuncAttributeMaxDynamicSharedMemorySize, SMEMSZ);
    cam_mma_kernel<<<128, 256, SMEMSZ>>>(x, gamma, out);
}